// round 13
// baseline (speedup 1.0000x reference)
#include <cuda_runtime.h>

// Problem constants (fixed by the dataset)
#define U_N 200000
#define M_N 100000
#define E_MAX 2000000
#define HD 64
#define CD 7
#define ROWSTRIDE 68   // 64 cols padded; multiple of 4 => float4-aligned rows

typedef unsigned long long u64;

// ---------------- scratch (device globals; no allocation allowed) ----------------
__device__ float g_xmovie[M_N * HD];
__device__ float g_u1p[U_N * 16];   // per user: [0:7] root-proj (u1@R2u), [8:15] agg-proj (u1@A2m)
__device__ float g_m1p[M_N * 16];   // per movie: [0:7] root-proj (m1@R2m), [8:15] agg-proj (m1@A2u)
__device__ float g_proj_u[U_N * CD];
__device__ float g_proj_m[M_N * CD];

// folded layer2+classifier matrices (64x7 each) and bias vectors
__device__ float g_A2u[448];   // l2_rev_Wl   @ clsW_u
__device__ float g_R2u[448];   // l2_rev_Wr   @ clsW_u
__device__ float g_A2m[448];   // l2_rates_Wl @ clsW_m
__device__ float g_R2m[448];   // l2_rates_Wr @ clsW_m
__device__ float g_cu[7];      // l2_rev_bl   @ clsW_u
__device__ float g_cm[7];      // l2_rates_bl @ clsW_m + clsb

__device__ int g_deg_u[U_N];
__device__ int g_off_u[U_N + 1];
__device__ int g_cur_u[U_N];
__device__ int g_deg_m[M_N];
__device__ int g_off_m[M_N + 1];
__device__ int g_cur_m[M_N];
__device__ int g_nbr_u[E_MAX];   // movie neighbor per user-grouped edge
__device__ int g_nbr_m[E_MAX];   // user neighbor per movie-grouped edge
__device__ int g_mode[4];        // 1 => indices are int64 on disk, 0 => int32

// ---------------- f32x2 packed-FMA helpers ----------------
__device__ __forceinline__ u64 pack2(float v) {
    u64 r;
    unsigned int b = __float_as_uint(v);
    asm("mov.b64 %0, {%1, %1};" : "=l"(r) : "r"(b));
    return r;
}
__device__ __forceinline__ u64 packf2(float lo, float hi) {
    u64 r;
    asm("mov.b64 %0, {%1, %2};" : "=l"(r) : "r"(__float_as_uint(lo)), "r"(__float_as_uint(hi)));
    return r;
}
__device__ __forceinline__ void fma2(u64& d, u64 a, u64 b) {
    asm("fma.rn.f32x2 %0, %1, %2, %0;" : "+l"(d) : "l"(a), "l"(b));
}
__device__ __forceinline__ float2 unpack2(u64 v) {
    unsigned int lo, hi;
    asm("mov.b64 {%0, %1}, %2;" : "=r"(lo), "=r"(hi) : "l"(v));
    return make_float2(__uint_as_float(lo), __uint_as_float(hi));
}

// ---------------- helpers ----------------
__device__ __forceinline__ int ld_idx(const int* __restrict__ p, int i, int m64) {
    return m64 ? p[2 * i] : p[i];
}

// detect int32/int64 for the 4 index arrays AND zero both degree arrays (merged launch)
__global__ void detect_zero_kernel(const int* es, const int* ed, const int* ls, const int* ld_) {
    int i = blockIdx.x * blockDim.x + threadIdx.x;
    if (i < U_N) g_deg_u[i] = 0;
    if (i < M_N) g_deg_m[i] = 0;
    if (blockIdx.x == 0 && threadIdx.x < 4) {
        int t = threadIdx.x;
        const int* p = (t == 0) ? es : (t == 1) ? ed : (t == 2) ? ls : ld_;
        int o = 0;
#pragma unroll
        for (int k = 0; k < 64; k++) o |= p[2 * k + 1];
        g_mode[t] = (o == 0) ? 1 : 0;
    }
}

__global__ void hist_kernel(const int* __restrict__ es, const int* __restrict__ ed, int E) {
    int m0 = g_mode[0], m1 = g_mode[1];
    for (int i = blockIdx.x * blockDim.x + threadIdx.x; i < E; i += gridDim.x * blockDim.x) {
        atomicAdd(&g_deg_u[ld_idx(es, i, m0)], 1);
        atomicAdd(&g_deg_m[ld_idx(ed, i, m1)], 1);
    }
}

// single-block exclusive scan body; writes cursor copy and off[n] = total
__device__ void scan_body(const int* __restrict__ deg, int* __restrict__ off,
                          int* __restrict__ cur, int n) {
    __shared__ int sh[1024];
    int tid = threadIdx.x;
    int chunk = (n + 1023) >> 10;
    int s0 = tid * chunk;
    int s1 = min(s0 + chunk, n);
    int sum = 0;
    for (int i = s0; i < s1; i++) sum += deg[i];
    sh[tid] = sum;
    __syncthreads();
    for (int d = 1; d < 1024; d <<= 1) {
        int v = (tid >= d) ? sh[tid - d] : 0;
        __syncthreads();
        sh[tid] += v;
        __syncthreads();
    }
    int run = (tid == 0) ? 0 : sh[tid - 1];
    for (int i = s0; i < s1; i++) {
        off[i] = run;
        cur[i] = run;
        run += deg[i];
    }
    if (tid == 0) off[n] = sh[1023];
}

// fold layer-2 weights through the classifier (runs as block 2 of scan_combine_kernel)
__device__ void combine_body(const float* __restrict__ l2rev_Wl, const float* __restrict__ l2rev_Wr,
                             const float* __restrict__ l2rev_bl,
                             const float* __restrict__ l2rates_Wl, const float* __restrict__ l2rates_Wr,
                             const float* __restrict__ l2rates_bl,
                             const float* __restrict__ clsW, const float* __restrict__ clsb) {
    int o = threadIdx.x;
    if (o < 448) {
        int k = o / 7, c = o - (o / 7) * 7;
        float a2u = 0.f, r2u = 0.f, a2m = 0.f, r2m = 0.f;
#pragma unroll
        for (int j = 0; j < 64; j++) {
            float wu = clsW[j * 7 + c];          // user half of cls_W (rows 0..63)
            float wm = clsW[(64 + j) * 7 + c];   // movie half (rows 64..127)
            a2u = fmaf(l2rev_Wl[k * 64 + j], wu, a2u);
            r2u = fmaf(l2rev_Wr[k * 64 + j], wu, r2u);
            a2m = fmaf(l2rates_Wl[k * 64 + j], wm, a2m);
            r2m = fmaf(l2rates_Wr[k * 64 + j], wm, r2m);
        }
        g_A2u[o] = a2u; g_R2u[o] = r2u; g_A2m[o] = a2m; g_R2m[o] = r2m;
    } else if (o < 455) {
        int c = o - 448;
        float cu = 0.f, cm = 0.f;
#pragma unroll
        for (int j = 0; j < 64; j++) {
            cu = fmaf(l2rev_bl[j], clsW[j * 7 + c], cu);
            cm = fmaf(l2rates_bl[j], clsW[(64 + j) * 7 + c], cm);
        }
        g_cu[c] = cu;
        g_cm[c] = cm + clsb[c];
    }
}

// block 0: user scan, block 1: movie scan, block 2: layer2/classifier weight fold
__global__ void scan_combine_kernel(const float* l2rev_Wl, const float* l2rev_Wr, const float* l2rev_bl,
                                    const float* l2rates_Wl, const float* l2rates_Wr, const float* l2rates_bl,
                                    const float* clsW, const float* clsb) {
    if (blockIdx.x == 0) scan_body(g_deg_u, g_off_u, g_cur_u, U_N);
    else if (blockIdx.x == 1) scan_body(g_deg_m, g_off_m, g_cur_m, M_N);
    else combine_body(l2rev_Wl, l2rev_Wr, l2rev_bl, l2rates_Wl, l2rates_Wr, l2rates_bl, clsW, clsb);
}

// ---------------- x_movie = movie_x @ w_movie + b_movie + movie_emb (smem-staged) ----------------
// 256 threads handle 16 movies; each thread computes one float4 (16 threads per movie).
// All operands staged in smem/registers — no exposed gmem latency in the FMA loop.
__global__ void __launch_bounds__(256) xmovie_kernel(const float* __restrict__ mx,
                                                     const float* __restrict__ w,
                                                     const float* __restrict__ b,
                                                     const float* __restrict__ emb) {
    __shared__ float sw[20 * 64];
    __shared__ float sxr[16 * 20];
    int tid = threadIdx.x;
    int base = blockIdx.x * 16;     // M_N % 16 == 0, grid covers exactly
    for (int i = tid; i < 1280; i += 256) sw[i] = w[i];
    // FIX (round 12): 320 > blockDim(256) — MUST stride (round-3 bug class)
    for (int i = tid; i < 320; i += 256) sxr[i] = mx[base * 20 + i];
    __syncthreads();

    int mv = tid >> 4;      // movie within block, 0..15
    int q = tid & 15;       // float4 column slot, 0..15
    int movie = base + mv;
    float4 acc = ((const float4*)b)[q];
    float4 ev = ((const float4*)emb)[movie * 16 + q];
    acc.x += ev.x; acc.y += ev.y; acc.z += ev.z; acc.w += ev.w;
#pragma unroll
    for (int f = 0; f < 20; f++) {
        float xr = sxr[mv * 20 + f];
        float4 wv = *(const float4*)&sw[f * 64 + q * 4];
        acc.x = fmaf(xr, wv.x, acc.x);
        acc.y = fmaf(xr, wv.y, acc.y);
        acc.z = fmaf(xr, wv.z, acc.z);
        acc.w = fmaf(xr, wv.w, acc.w);
    }
    ((float4*)g_xmovie)[movie * 16 + q] = acc;
}

__global__ void fill_kernel(const int* __restrict__ es, const int* __restrict__ ed, int E) {
    int m0 = g_mode[0], m1 = g_mode[1];
    for (int i = blockIdx.x * blockDim.x + threadIdx.x; i < E; i += gridDim.x * blockDim.x) {
        int s = ld_idx(es, i, m0);
        int d = ld_idx(ed, i, m1);
        int pu = atomicAdd(&g_cur_u[s], 1);
        g_nbr_u[pu] = d;
        int pm = atomicAdd(&g_cur_m[d], 1);
        g_nbr_m[pm] = s;
    }
}

// ---------------- fused SAGE layer-1 body ----------------
// One block = 64 nodes. Fused: mean-agg gather -> dual-weight GEMM (packed f32x2 FMA)
// -> bias -> relu -> dual 64->7 projection through folded layer-2 matrices.
__device__ __forceinline__ void sage_body(
    int blk, const float* __restrict__ xsrc, const float* __restrict__ Xroot,
    const int* __restrict__ off, const int* __restrict__ nbr,
    const float* __restrict__ Wl, const float* __restrict__ Wr,
    const float* __restrict__ bias, int N,
    const float* __restrict__ Rmat, const float* __restrict__ Amat,
    float* __restrict__ dst) {
    extern __shared__ float sh[];
    float* sWl = sh;                       // 64*64
    float* sWr = sh + 4096;                // 64*64
    float* sA  = sh + 8192;                // 64*68
    float* sX  = sA + 64 * ROWSTRIDE;      // 64*68
    int tid = threadIdx.x;
    int nb = blk * 64;

    // weights -> smem (coalesced float4)
    {
        const float4* wl4 = (const float4*)Wl;
        const float4* wr4 = (const float4*)Wr;
        float4* sl = (float4*)sWl;
        float4* sr = (float4*)sWr;
#pragma unroll
        for (int i = 0; i < 4; i++) {
            sl[tid + 256 * i] = wl4[tid + 256 * i];
            sr[tid + 256 * i] = wr4[tid + 256 * i];
        }
    }

    // ---- fused mean aggregation: warp per node, 8 rounds, float2 per lane ----
    {
        int warp = tid >> 5;
        int lane = tid & 31;
#pragma unroll
        for (int it = 0; it < 8; it++) {
            int r = warp * 8 + it;
            int node = nb + r;
            float a0 = 0.f, a1 = 0.f;
            if (node < N) {
                int s = __ldg(&off[node]);
                int e = __ldg(&off[node + 1]);
                int j = s;
                for (; j + 8 <= e; j += 8) {
                    int n0 = __ldg(&nbr[j]);
                    int n1 = __ldg(&nbr[j + 1]);
                    int n2 = __ldg(&nbr[j + 2]);
                    int n3 = __ldg(&nbr[j + 3]);
                    int n4 = __ldg(&nbr[j + 4]);
                    int n5 = __ldg(&nbr[j + 5]);
                    int n6 = __ldg(&nbr[j + 6]);
                    int n7 = __ldg(&nbr[j + 7]);
                    float2 v0 = ((const float2*)(xsrc + n0 * 64))[lane];
                    float2 v1 = ((const float2*)(xsrc + n1 * 64))[lane];
                    float2 v2 = ((const float2*)(xsrc + n2 * 64))[lane];
                    float2 v3 = ((const float2*)(xsrc + n3 * 64))[lane];
                    float2 v4 = ((const float2*)(xsrc + n4 * 64))[lane];
                    float2 v5 = ((const float2*)(xsrc + n5 * 64))[lane];
                    float2 v6 = ((const float2*)(xsrc + n6 * 64))[lane];
                    float2 v7 = ((const float2*)(xsrc + n7 * 64))[lane];
                    a0 += v0.x + v1.x + v2.x + v3.x + v4.x + v5.x + v6.x + v7.x;
                    a1 += v0.y + v1.y + v2.y + v3.y + v4.y + v5.y + v6.y + v7.y;
                }
                for (; j < e; j++) {
                    float2 v = ((const float2*)(xsrc + __ldg(&nbr[j]) * 64))[lane];
                    a0 += v.x;
                    a1 += v.y;
                }
                float inv = 1.0f / (float)max(e - s, 1);
                a0 *= inv;
                a1 *= inv;
            }
            *(float2*)&sA[r * ROWSTRIDE + lane * 2] = make_float2(a0, a1);
        }
    }

    // ---- root features -> smem (coalesced float4) ----
#pragma unroll
    for (int i = 0; i < 4; i++) {
        int f = tid + 256 * i;       // float4 slot id, 0..1023
        int r = f >> 4;              // row 0..63
        int cc = f & 15;             // float4 col 0..15
        int gr = nb + r;
        float4 vx = make_float4(0.f, 0.f, 0.f, 0.f);
        if (gr < N) vx = ((const float4*)Xroot)[gr * 16 + cc];
        *(float4*)&sX[r * ROWSTRIDE + cc * 4] = vx;
    }
    __syncthreads();

    // ---- mainloop: 4x4 register tile, k blocked by 4, packed f32x2 FMA ----
    int ty = tid >> 4, tx = tid & 15;
    int r0 = ty * 4, c0 = tx * 4;
    u64 acc01[4], acc23[4];   // per row i: packed cols (c0,c0+1) and (c0+2,c0+3)
#pragma unroll
    for (int i = 0; i < 4; i++) { acc01[i] = 0ull; acc23[i] = 0ull; }

#pragma unroll
    for (int kb = 0; kb < 64; kb += 4) {
        float4 A4[4], X4[4];
#pragma unroll
        for (int i = 0; i < 4; i++) {
            A4[i] = *(const float4*)&sA[(r0 + i) * ROWSTRIDE + kb];
            X4[i] = *(const float4*)&sX[(r0 + i) * ROWSTRIDE + kb];
        }
#pragma unroll
        for (int kk = 0; kk < 4; kk++) {
            float4 wl = *(const float4*)&sWl[(kb + kk) * 64 + c0];
            float4 wr = *(const float4*)&sWr[(kb + kk) * 64 + c0];
            u64 wl01 = packf2(wl.x, wl.y);
            u64 wl23 = packf2(wl.z, wl.w);
            u64 wr01 = packf2(wr.x, wr.y);
            u64 wr23 = packf2(wr.z, wr.w);
#pragma unroll
            for (int i = 0; i < 4; i++) {
                u64 aa = pack2(((const float*)&A4[i])[kk]);
                u64 xx = pack2(((const float*)&X4[i])[kk]);
                fma2(acc01[i], aa, wl01);
                fma2(acc01[i], xx, wr01);
                fma2(acc23[i], aa, wl23);
                fma2(acc23[i], xx, wr23);
            }
        }
    }

    float4 bv = *(const float4*)&bias[c0];

    // ---- epilogue: bias + relu tile -> smem, dual 64->7 projection -> dst ----
    __syncthreads();   // all mainloop smem reads complete before overwrite
#pragma unroll
    for (int i = 0; i < 4; i++) {
        float2 p01 = unpack2(acc01[i]);
        float2 p23 = unpack2(acc23[i]);
        float4 v;
        v.x = fmaxf(p01.x + bv.x, 0.f);
        v.y = fmaxf(p01.y + bv.y, 0.f);
        v.z = fmaxf(p23.x + bv.z, 0.f);
        v.w = fmaxf(p23.y + bv.w, 0.f);
        *(float4*)&sA[(r0 + i) * ROWSTRIDE + c0] = v;
    }
    // folded projection matrices: R in sWl[0:448], A in sWl[448:896]
    for (int i2 = tid; i2 < 896; i2 += 256)
        sWl[i2] = (i2 < 448) ? Rmat[i2] : Amat[i2 - 448];
    __syncthreads();
    for (int o = tid; o < 448; o += 256) {
        int nl = o / 7;
        int c = o - nl * 7;
        int gr = nb + nl;
        if (gr < N) {
            float r = 0.f, a = 0.f;
#pragma unroll
            for (int k = 0; k < 64; k++) {
                float v = sA[nl * ROWSTRIDE + k];
                r = fmaf(v, sWl[k * 7 + c], r);
                a = fmaf(v, sWl[448 + k * 7 + c], a);
            }
            dst[gr * 16 + c] = r;        // root slot
            dst[gr * 16 + 8 + c] = a;    // agg slot
        }
    }
}

// user blocks then movie blocks in one grid
__global__ void __launch_bounds__(256, 3) layer1_kernel(
    int guBlocks,
    const float* __restrict__ user_emb,
    const float* __restrict__ Wl_u, const float* __restrict__ Wr_u, const float* __restrict__ b_u,
    const float* __restrict__ Wl_m, const float* __restrict__ Wr_m, const float* __restrict__ b_m) {
    if ((int)blockIdx.x < guBlocks) {
        sage_body(blockIdx.x, g_xmovie, user_emb, g_off_u, g_nbr_u,
                  Wl_u, Wr_u, b_u, U_N, g_R2u, g_A2m, g_u1p);
    } else {
        sage_body(blockIdx.x - guBlocks, user_emb, g_xmovie, g_off_m, g_nbr_m,
                  Wl_m, Wr_m, b_m, M_N, g_R2m, g_A2u, g_m1p);
    }
}

// ---------------- layer 2 (7-wide): proj = mean-agg(peer agg-proj) + own root-proj + c ----------------
// Half-warp per node: lanes {0..6} and {16..22} each own one node's 7 channels.
__global__ void proj_agg_kernel() {
    int w = (blockIdx.x * blockDim.x + threadIdx.x) >> 5;
    int lane = threadIdx.x & 31;
    int half = lane >> 4;
    int c = lane & 15;
    int gnode = w * 2 + half;
    if (c >= 7 || gnode >= U_N + M_N) return;
    bool isU = gnode < U_N;
    int node = isU ? gnode : gnode - U_N;
    const int* off = isU ? g_off_u : g_off_m;
    const int* nbr = isU ? g_nbr_u : g_nbr_m;
    const float* srcp = isU ? g_m1p : g_u1p;    // aggregate peer's agg-proj slot
    const float* rootp = isU ? g_u1p : g_m1p;   // own root-proj slot
    const float* cv = isU ? g_cu : g_cm;
    float* dst = isU ? g_proj_u : g_proj_m;

    int s = __ldg(&off[node]);
    int e = __ldg(&off[node + 1]);
    float sum = 0.f;
    int j = s;
    for (; j + 4 <= e; j += 4) {
        int n0 = __ldg(&nbr[j]);
        int n1 = __ldg(&nbr[j + 1]);
        int n2 = __ldg(&nbr[j + 2]);
        int n3 = __ldg(&nbr[j + 3]);
        sum += srcp[n0 * 16 + 8 + c] + srcp[n1 * 16 + 8 + c] +
               srcp[n2 * 16 + 8 + c] + srcp[n3 * 16 + 8 + c];
    }
    for (; j < e; j++) sum += srcp[__ldg(&nbr[j]) * 16 + 8 + c];
    float inv = 1.0f / (float)max(e - s, 1);
    dst[node * 7 + c] = sum * inv + rootp[node * 16 + c] + cv[c];
}

// ---------------- final edge output: out[e][c] = proj_u[src][c] + proj_m[dst][c] ----------------
__global__ void final_kernel(const int* __restrict__ ls, const int* __restrict__ ld_,
                             float* __restrict__ out, int EL) {
    int m2 = g_mode[2], m3 = g_mode[3];
    int total = EL * 7;
    for (int idx = blockIdx.x * blockDim.x + threadIdx.x; idx < total;
         idx += gridDim.x * blockDim.x) {
        int e = idx / 7;
        int c = idx - e * 7;
        int s = ld_idx(ls, e, m2);
        int d = ld_idx(ld_, e, m3);
        out[idx] = g_proj_u[s * 7 + c] + g_proj_m[d * 7 + c];
    }
}

// ---------------- launch ----------------
extern "C" void kernel_launch(void* const* d_in, const int* in_sizes, int n_in,
                              void* d_out, int out_size) {
    const float* movie_x = (const float*)d_in[2];
    const int* edge_src = (const int*)d_in[3];
    const int* edge_dst = (const int*)d_in[4];
    const int* el_src = (const int*)d_in[5];
    const int* el_dst = (const int*)d_in[6];
    const float* user_emb = (const float*)d_in[7];
    const float* movie_emb = (const float*)d_in[8];
    const float* w_movie = (const float*)d_in[9];
    const float* b_movie = (const float*)d_in[10];
    const float* l1_rates_Wl = (const float*)d_in[11];
    const float* l1_rates_bl = (const float*)d_in[12];
    const float* l1_rates_Wr = (const float*)d_in[13];
    const float* l1_rev_Wl = (const float*)d_in[14];
    const float* l1_rev_bl = (const float*)d_in[15];
    const float* l1_rev_Wr = (const float*)d_in[16];
    const float* l2_rates_Wl = (const float*)d_in[17];
    const float* l2_rates_bl = (const float*)d_in[18];
    const float* l2_rates_Wr = (const float*)d_in[19];
    const float* l2_rev_Wl = (const float*)d_in[20];
    const float* l2_rev_bl = (const float*)d_in[21];
    const float* l2_rev_Wr = (const float*)d_in[22];
    const float* cls_W = (const float*)d_in[23];
    const float* cls_b = (const float*)d_in[24];
    float* out = (float*)d_out;

    int E = in_sizes[3];
    if (E > E_MAX) E = E_MAX;
    int EL = out_size / 7;

    const int SMEM = (8192 + 2 * 64 * ROWSTRIDE) * 4;  // 67584 bytes
    cudaFuncSetAttribute(layer1_kernel, cudaFuncAttributeMaxDynamicSharedMemorySize, SMEM);

    int gu = (U_N + 63) / 64;
    int gm = (M_N + 63) / 64;

    // 1. dtype detect + degree zero (merged)
    detect_zero_kernel<<<(U_N + 255) / 256, 256>>>(edge_src, edge_dst, el_src, el_dst);
    // 2. degree histogram
    hist_kernel<<<1184, 256>>>(edge_src, edge_dst, E);
    // 3. offset scans (blocks 0-1) + layer2/classifier weight fold (block 2)
    scan_combine_kernel<<<3, 1024>>>(l2_rev_Wl, l2_rev_Wr, l2_rev_bl,
                                     l2_rates_Wl, l2_rates_Wr, l2_rates_bl, cls_W, cls_b);
    // 4. movie input projection (smem-staged, no exposed latency)
    xmovie_kernel<<<M_N / 16, 256>>>(movie_x, w_movie, b_movie, movie_emb);
    // 5. CSR fill (both directions)
    fill_kernel<<<1184, 256>>>(edge_src, edge_dst, E);

    // 6. layer 1: fused agg + f32x2 GEMM + relu + dual 64->7 projection (one grid)
    layer1_kernel<<<gu + gm, 256, SMEM>>>(gu, user_emb,
                                          l1_rev_Wl, l1_rev_Wr, l1_rev_bl,
                                          l1_rates_Wl, l1_rates_Wr, l1_rates_bl);
    // 7. layer 2 collapsed to 7-wide mean gather + root add (one grid)
    {
        int warps = (U_N + M_N + 1) / 2;          // half-warp per node
        int blocks = (warps * 32 + 255) / 256;
        proj_agg_kernel<<<blocks, 256>>>();
    }
    // 8. per-edge gather-add of the two 7-wide projections
    final_kernel<<<(EL * 7 + 255) / 256, 256>>>(el_src, el_dst, out, EL);
}